// round 15
// baseline (speedup 1.0000x reference)
#include <cuda_runtime.h>
#include <math.h>

// Problem constants (fixed shapes from reference)
#define Bq 2
#define Nq 1024
#define DIN 64
#define Hh 4
#define Pp 16
#define Dm 64                // Hh*Pp
#define SPLITS 16
#define CHUNK (Nq / SPLITS)  // 64 j per split
#define TI 128               // i rows per block (2 per thread)
#define NW (Nq / 32)         // mask words per row = 32

typedef unsigned long long u64;

#define ADD_F32X2(d, a, b) \
    asm("add.rn.f32x2 %0, %1, %2;" : "=l"(d) : "l"(a), "l"(b))
#define FMA_F32X2(d, a, b, c) \
    asm("fma.rn.f32x2 %0, %1, %2, %3;" : "=l"(d) : "l"(a), "l"(b), "l"(c))

__device__ __forceinline__ u64 pack2(float lo, float hi) {
    u64 d;
    asm("mov.b64 %0, {%1, %2};" : "=l"(d) : "r"(__float_as_uint(lo)), "r"(__float_as_uint(hi)));
    return d;
}
__device__ __forceinline__ void unpack2(u64 v, float& lo, float& hi) {
    unsigned a, b;
    asm("mov.b64 {%0, %1}, %2;" : "=r"(a), "=r"(b) : "l"(v));
    lo = __uint_as_float(a);
    hi = __uint_as_float(b);
}

// ---------------- scratch (device globals; no allocation allowed) ----------
__device__ float               g_ne[Nq * DIN];
__device__ unsigned            g_mask[Nq * NW];
__device__ __align__(16) float g_xl[Bq * Nq * Dm];
__device__ __align__(16) float g_xr[Bq * Nq * Dm];
__device__ __align__(16) float g_pacc[(size_t)SPLITS * Bq * Nq * Dm];  // 8 MB
__device__ float               g_ps[SPLITS * Bq * Nq * Hh];
__device__ __align__(16) float g_hbuf[Bq * Nq * Dm];

// ---------------- 1) normalize embedding rows ------------------------------
__global__ void norm_kernel(const float* __restrict__ emb) {
    int r = blockIdx.x * blockDim.x + threadIdx.x;
    if (r >= Nq) return;
    float s = 0.f;
    #pragma unroll 8
    for (int k = 0; k < DIN; ++k) {
        float v = emb[r * DIN + k];
        s = fmaf(v, v, s);
    }
    float n = fmaxf(sqrtf(s), 1e-12f);
    float inv = 1.0f / n;
    #pragma unroll 8
    for (int k = 0; k < DIN; ++k)
        g_ne[r * DIN + k] = emb[r * DIN + k] * inv;
}

// ---------------- 2) mask: (ne_i . ne_j != 0) || (i==j) --------------------
__global__ void mask_kernel() {
    __shared__ float shi[8][DIN];
    __shared__ float shj[32 * 65];
    int t = threadIdx.x;  // 256
    int i0 = blockIdx.x * 8;
    for (int k = t; k < 8 * DIN; k += 256)
        shi[k / DIN][k % DIN] = g_ne[i0 * DIN + k];
    int w = t >> 5, lane = t & 31;
    int i = i0 + w;
    for (int jt = 0; jt < NW; ++jt) {
        __syncthreads();
        for (int k = t; k < 32 * DIN; k += 256) {
            int r = k / DIN, c = k % DIN;
            shj[r * 65 + c] = g_ne[(jt * 32 + r) * DIN + c];
        }
        __syncthreads();
        float d = 0.f;
        #pragma unroll 8
        for (int k = 0; k < DIN; ++k)
            d = fmaf(shi[w][k], shj[lane * 65 + k], d);
        int j = jt * 32 + lane;
        bool bit = (d != 0.0f) || (i == j);
        unsigned word = __ballot_sync(0xffffffffu, bit);
        if (lane == 0) g_mask[i * NW + jt] = word;
    }
}

// ---------------- 3) dual GEMM: xl = X@Wl, xr = X@Wr -----------------------
__global__ void gemm_dual(const float* __restrict__ Xext, int use_gh,
                          const float* __restrict__ Wl,
                          const float* __restrict__ Wr) {
    __shared__ float xs[16][DIN];
    const float* X = use_gh ? g_hbuf : Xext;
    int t = threadIdx.x;  // 128
    int row0 = blockIdx.x * 16;
    for (int k = t; k < 16 * DIN; k += 128)
        xs[k / DIN][k % DIN] = X[row0 * DIN + k];
    __syncthreads();
    const float* W = (t < 64) ? Wl : Wr;
    int col = t & 63;
    float wreg[DIN];
    #pragma unroll
    for (int k = 0; k < DIN; ++k) wreg[k] = W[k * Dm + col];
    float* out = (t < 64) ? g_xl : g_xr;
    for (int r = 0; r < 16; ++r) {
        float a = 0.f;
        #pragma unroll
        for (int k = 0; k < DIN; ++k) a = fmaf(xs[r][k], wreg[k], a);
        out[(row0 + r) * Dm + col] = a;
    }
}

// ---------------- 4) fused attention (per j-split partials) ----------------
// block: 256 threads = 64 i-slots x 4 h; each thread handles 2 i rows.
// grid (Nq/TI, Bq, SPLITS)
__global__ void __launch_bounds__(256, 2) attn_kernel(const float* __restrict__ att) {
    __shared__ __align__(16) float sxl[CHUNK * Dm];   // 16 KB
    __shared__ float scl[CHUNK * Hh];                 // 1 KB
    __shared__ unsigned smask[TI * (CHUNK / 32)];     // 128*2

    int t = threadIdx.x;
    int b = blockIdx.y, split = blockIdx.z;
    int i0 = blockIdx.x * TI;
    int j0 = split * CHUNK;

    // stage xl j-chunk into shared
    {
        const float4* src = reinterpret_cast<const float4*>(g_xl + (size_t)(b * Nq + j0) * Dm);
        float4* dst = reinterpret_cast<float4*>(sxl);
        for (int k = t; k < CHUNK * Dm / 4; k += 256) dst[k] = src[k];
    }
    // stage mask words (TI rows x 2 words = 256)
    {
        int il = t >> 1, ww = t & 1;
        smask[t] = g_mask[(i0 + il) * NW + (j0 >> 5) + ww];
    }
    __syncthreads();
    // scl[jj,h] = 0.6 * sum_p att[h,p] * xl[j0+jj, h, p]   (one thread each)
    {
        int jj = t >> 2, hh = t & 3;
        float c = 0.f;
        #pragma unroll
        for (int p = 0; p < Pp; ++p)
            c = fmaf(att[hh * Pp + p], sxl[jj * Dm + hh * Pp + p], c);
        scl[jj * Hh + hh] = 0.6f * c;
    }

    int il = t >> 2, h = t & 3;
    int iA = i0 + il;
    int iB = i0 + il + 64;

    // packed 0.4*att for this head
    u64 at2[8];
    #pragma unroll
    for (int k = 0; k < 8; ++k)
        at2[k] = pack2(0.4f * att[h * Pp + 2 * k], 0.4f * att[h * Pp + 2 * k + 1]);

    // packed xr rows for both i
    u64 xrA[8], xrB[8];
    {
        const ulonglong2* pA =
            reinterpret_cast<const ulonglong2*>(g_xr + ((size_t)(b * Nq + iA)) * Dm + h * Pp);
        const ulonglong2* pB =
            reinterpret_cast<const ulonglong2*>(g_xr + ((size_t)(b * Nq + iB)) * Dm + h * Pp);
        #pragma unroll
        for (int q = 0; q < 4; ++q) {
            ulonglong2 ua = pA[q];
            xrA[2 * q] = ua.x; xrA[2 * q + 1] = ua.y;
            ulonglong2 ub = pB[q];
            xrB[2 * q] = ub.x; xrB[2 * q + 1] = ub.y;
        }
    }

    // ci = 0.6 * sum_p att*xr = 1.5 * sum_p (0.4att)*xr
    float ciA, ciB;
    {
        u64 cA = 0ull, cB = 0ull;
        #pragma unroll
        for (int k = 0; k < 8; ++k) {
            FMA_F32X2(cA, at2[k], xrA[k], cA);
            FMA_F32X2(cB, at2[k], xrB[k], cB);
        }
        float lo, hi;
        unpack2(cA, lo, hi); ciA = 1.5f * (lo + hi);
        unpack2(cB, lo, hi); ciB = 1.5f * (lo + hi);
    }

    u64 accA[8], accB[8];
    #pragma unroll
    for (int k = 0; k < 8; ++k) { accA[k] = 0ull; accB[k] = 0ull; }
    float sA = 0.f, sB = 0.f;

    __syncthreads();  // scl ready

    unsigned mA[2], mB[2];
    mA[0] = smask[il * 2];        mA[1] = smask[il * 2 + 1];
    mB[0] = smask[(il + 64) * 2]; mB[1] = smask[(il + 64) * 2 + 1];

    const u64 ABSM = 0x7FFFFFFF7FFFFFFFull;

    #pragma unroll 1
    for (int w2 = 0; w2 < CHUNK / 32; ++w2) {
        unsigned maskA = mA[w2], maskB = mB[w2];
        #pragma unroll 4
        for (int jb = 0; jb < 32; ++jb) {
            int jj = w2 * 32 + jb;
            const ulonglong2* xp =
                reinterpret_cast<const ulonglong2*>(&sxl[jj * Dm + h * Pp]);
            u64 xl2[8];
            #pragma unroll
            for (int q = 0; q < 4; ++q) {
                ulonglong2 u = xp[q];
                xl2[2 * q] = u.x; xl2[2 * q + 1] = u.y;
            }
            float cj = scl[jj * Hh + h];

            u64 eA2 = 0ull, eB2 = 0ull;
            #pragma unroll
            for (int k = 0; k < 8; ++k) {
                u64 vA; ADD_F32X2(vA, xrA[k], xl2[k]);
                vA &= ABSM;
                FMA_F32X2(eA2, at2[k], vA, eA2);
                u64 vB; ADD_F32X2(vB, xrB[k], xl2[k]);
                vB &= ABSM;
                FMA_F32X2(eB2, at2[k], vB, eB2);
            }
            float lo, hi;
            unpack2(eA2, lo, hi);
            float eA = (ciA + cj) + (lo + hi);
            unpack2(eB2, lo, hi);
            float eB = (ciB + cj) + (lo + hi);

            float wA = ((maskA >> jb) & 1u) ? __expf(eA) : 0.0f;
            float wB = ((maskB >> jb) & 1u) ? __expf(eB) : 0.0f;
            sA += wA; sB += wB;
            u64 wA2 = pack2(wA, wA);
            u64 wB2 = pack2(wB, wB);
            #pragma unroll
            for (int k = 0; k < 8; ++k) {
                FMA_F32X2(accA[k], wA2, xl2[k], accA[k]);
                FMA_F32X2(accB[k], wB2, xl2[k], accB[k]);
            }
        }
    }

    // store partials
    {
        ulonglong2* pA = reinterpret_cast<ulonglong2*>(
            g_pacc + ((size_t)(split * Bq + b) * Nq + iA) * Dm + h * Pp);
        ulonglong2* pB = reinterpret_cast<ulonglong2*>(
            g_pacc + ((size_t)(split * Bq + b) * Nq + iB) * Dm + h * Pp);
        #pragma unroll
        for (int q = 0; q < 4; ++q) {
            pA[q] = make_ulonglong2(accA[2 * q], accA[2 * q + 1]);
            pB[q] = make_ulonglong2(accB[2 * q], accB[2 * q + 1]);
        }
    }
    g_ps[((split * Bq + b) * Nq + iA) * Hh + h] = sA;
    g_ps[((split * Bq + b) * Nq + iB) * Hh + h] = sB;
}

// ---------------- 5) combine splits, normalize, bias, (relu) ---------------
__global__ void combine_kernel(const float* __restrict__ bias,
                               float* __restrict__ outext, int mode) {
    int id = blockIdx.x * blockDim.x + threadIdx.x;  // Bq*Nq*Dm
    if (id >= Bq * Nq * Dm) return;
    int c = id & (Dm - 1);
    int row = id >> 6;  // b*Nq + i
    int h = c >> 4;
    float s = 0.f, a = 0.f;
    #pragma unroll
    for (int sp = 0; sp < SPLITS; ++sp) {
        s += g_ps[(sp * Bq * Nq + row) * Hh + h];
        a += g_pacc[((size_t)sp * Bq * Nq + row) * Dm + c];
    }
    float o = a / s + bias[c];
    if (mode) {
        g_hbuf[id] = fmaxf(o, 0.0f);
    } else {
        outext[id] = o;
    }
}

// ---------------- driver ----------------------------------------------------
extern "C" void kernel_launch(void* const* d_in, const int* in_sizes, int n_in,
                              void* d_out, int out_size) {
    const float* x    = (const float*)d_in[0];
    const float* emb  = (const float*)d_in[1];
    const float* Wl1  = (const float*)d_in[2];
    const float* Wr1  = (const float*)d_in[3];
    const float* att1 = (const float*)d_in[4];
    const float* b1   = (const float*)d_in[5];
    const float* Wl2  = (const float*)d_in[6];
    const float* Wr2  = (const float*)d_in[7];
    const float* att2 = (const float*)d_in[8];
    const float* b2   = (const float*)d_in[9];
    float* out = (float*)d_out;

    norm_kernel<<<(Nq + 255) / 256, 256>>>(emb);
    mask_kernel<<<Nq / 8, 256>>>();

    dim3 agrid(Nq / TI, Bq, SPLITS);

    // ---- layer 1 ----
    gemm_dual<<<Bq * Nq / 16, 128>>>(x, 0, Wl1, Wr1);
    attn_kernel<<<agrid, 256>>>(att1);
    combine_kernel<<<(Bq * Nq * Dm + 255) / 256, 256>>>(b1, out, 1);

    // ---- layer 2 ----
    gemm_dual<<<Bq * Nq / 16, 128>>>(x, 1, Wl2, Wr2);
    attn_kernel<<<agrid, 256>>>(att2);
    combine_kernel<<<(Bq * Nq * Dm + 255) / 256, 256>>>(b2, out, 0);
}

// round 16
// speedup vs baseline: 1.0014x; 1.0014x over previous
#include <cuda_runtime.h>
#include <math.h>

// Problem constants (fixed shapes from reference)
#define Bq 2
#define Nq 1024
#define DIN 64
#define Hh 4
#define Pp 16
#define Dm 64                // Hh*Pp
#define SPLITS 16
#define CHUNK (Nq / SPLITS)  // 64 j per split
#define TI 128               // i rows per block (2 per thread)
#define NW (Nq / 32)         // mask words per row = 32

typedef unsigned long long u64;

#define ADD_F32X2(d, a, b) \
    asm("add.rn.f32x2 %0, %1, %2;" : "=l"(d) : "l"(a), "l"(b))
#define FMA_F32X2(d, a, b, c) \
    asm("fma.rn.f32x2 %0, %1, %2, %3;" : "=l"(d) : "l"(a), "l"(b), "l"(c))

__device__ __forceinline__ u64 pack2(float lo, float hi) {
    u64 d;
    asm("mov.b64 %0, {%1, %2};" : "=l"(d) : "r"(__float_as_uint(lo)), "r"(__float_as_uint(hi)));
    return d;
}
__device__ __forceinline__ void unpack2(u64 v, float& lo, float& hi) {
    unsigned a, b;
    asm("mov.b64 {%0, %1}, %2;" : "=r"(a), "=r"(b) : "l"(v));
    lo = __uint_as_float(a);
    hi = __uint_as_float(b);
}

// ---------------- scratch (device globals; no allocation allowed) ----------
__device__ float               g_ne[Nq * DIN];
__device__ unsigned            g_mask[Nq * NW];
__device__ __align__(16) float g_xl[Bq * Nq * Dm];
__device__ __align__(16) float g_xr[Bq * Nq * Dm];
__device__ __align__(16) float g_pacc[(size_t)SPLITS * Bq * Nq * Dm];  // 8 MB
__device__ float               g_ps[SPLITS * Bq * Nq * Hh];
__device__ __align__(16) float g_hbuf[Bq * Nq * Dm];

// ---------------- 1) normalize embedding rows ------------------------------
__global__ void norm_kernel(const float* __restrict__ emb) {
    int r = blockIdx.x * blockDim.x + threadIdx.x;
    if (r >= Nq) return;
    float s = 0.f;
    #pragma unroll 8
    for (int k = 0; k < DIN; ++k) {
        float v = emb[r * DIN + k];
        s = fmaf(v, v, s);
    }
    float n = fmaxf(sqrtf(s), 1e-12f);
    float inv = 1.0f / n;
    #pragma unroll 8
    for (int k = 0; k < DIN; ++k)
        g_ne[r * DIN + k] = emb[r * DIN + k] * inv;
}

// ---------------- 2) mask: (ne_i . ne_j != 0) || (i==j) --------------------
__global__ void mask_kernel() {
    __shared__ float shi[8][DIN];
    __shared__ float shj[32 * 65];
    int t = threadIdx.x;  // 256
    int i0 = blockIdx.x * 8;
    for (int k = t; k < 8 * DIN; k += 256)
        shi[k / DIN][k % DIN] = g_ne[i0 * DIN + k];
    int w = t >> 5, lane = t & 31;
    int i = i0 + w;
    for (int jt = 0; jt < NW; ++jt) {
        __syncthreads();
        for (int k = t; k < 32 * DIN; k += 256) {
            int r = k / DIN, c = k % DIN;
            shj[r * 65 + c] = g_ne[(jt * 32 + r) * DIN + c];
        }
        __syncthreads();
        float d = 0.f;
        #pragma unroll 8
        for (int k = 0; k < DIN; ++k)
            d = fmaf(shi[w][k], shj[lane * 65 + k], d);
        int j = jt * 32 + lane;
        bool bit = (d != 0.0f) || (i == j);
        unsigned word = __ballot_sync(0xffffffffu, bit);
        if (lane == 0) g_mask[i * NW + jt] = word;
    }
}

// ---------------- 3) dual GEMM: xl = X@Wl, xr = X@Wr -----------------------
__global__ void gemm_dual(const float* __restrict__ Xext, int use_gh,
                          const float* __restrict__ Wl,
                          const float* __restrict__ Wr) {
    __shared__ float xs[16][DIN];
    const float* X = use_gh ? g_hbuf : Xext;
    int t = threadIdx.x;  // 128
    int row0 = blockIdx.x * 16;
    for (int k = t; k < 16 * DIN; k += 128)
        xs[k / DIN][k % DIN] = X[row0 * DIN + k];
    __syncthreads();
    const float* W = (t < 64) ? Wl : Wr;
    int col = t & 63;
    float wreg[DIN];
    #pragma unroll
    for (int k = 0; k < DIN; ++k) wreg[k] = W[k * Dm + col];
    float* out = (t < 64) ? g_xl : g_xr;
    for (int r = 0; r < 16; ++r) {
        float a = 0.f;
        #pragma unroll
        for (int k = 0; k < DIN; ++k) a = fmaf(xs[r][k], wreg[k], a);
        out[(row0 + r) * Dm + col] = a;
    }
}

// ---------------- 4) fused attention (per j-split partials) ----------------
// block: 256 threads = 64 i-slots x 4 h; each thread handles 2 i rows.
// grid (Nq/TI, Bq, SPLITS)
__global__ void __launch_bounds__(256, 2) attn_kernel(const float* __restrict__ att) {
    __shared__ __align__(16) float sxl[CHUNK * Dm];   // 16 KB
    __shared__ float scl[CHUNK * Hh];                 // 1 KB
    __shared__ unsigned smask[TI * (CHUNK / 32)];     // 128*2

    int t = threadIdx.x;
    int b = blockIdx.y, split = blockIdx.z;
    int i0 = blockIdx.x * TI;
    int j0 = split * CHUNK;

    // stage xl j-chunk into shared
    {
        const float4* src = reinterpret_cast<const float4*>(g_xl + (size_t)(b * Nq + j0) * Dm);
        float4* dst = reinterpret_cast<float4*>(sxl);
        for (int k = t; k < CHUNK * Dm / 4; k += 256) dst[k] = src[k];
    }
    // stage mask words (TI rows x 2 words = 256)
    {
        int il = t >> 1, ww = t & 1;
        smask[t] = g_mask[(i0 + il) * NW + (j0 >> 5) + ww];
    }
    __syncthreads();
    // scl[jj,h] = 0.6 * sum_p att[h,p] * xl[j0+jj, h, p]   (one thread each)
    {
        int jj = t >> 2, hh = t & 3;
        float c = 0.f;
        #pragma unroll
        for (int p = 0; p < Pp; ++p)
            c = fmaf(att[hh * Pp + p], sxl[jj * Dm + hh * Pp + p], c);
        scl[jj * Hh + hh] = 0.6f * c;
    }

    int il = t >> 2, h = t & 3;
    int iA = i0 + il;
    int iB = i0 + il + 64;

    // packed 0.4*att for this head
    u64 at2[8];
    #pragma unroll
    for (int k = 0; k < 8; ++k)
        at2[k] = pack2(0.4f * att[h * Pp + 2 * k], 0.4f * att[h * Pp + 2 * k + 1]);

    // packed xr rows for both i
    u64 xrA[8], xrB[8];
    {
        const ulonglong2* pA =
            reinterpret_cast<const ulonglong2*>(g_xr + ((size_t)(b * Nq + iA)) * Dm + h * Pp);
        const ulonglong2* pB =
            reinterpret_cast<const ulonglong2*>(g_xr + ((size_t)(b * Nq + iB)) * Dm + h * Pp);
        #pragma unroll
        for (int q = 0; q < 4; ++q) {
            ulonglong2 ua = pA[q];
            xrA[2 * q] = ua.x; xrA[2 * q + 1] = ua.y;
            ulonglong2 ub = pB[q];
            xrB[2 * q] = ub.x; xrB[2 * q + 1] = ub.y;
        }
    }

    // ci = 0.6 * sum_p att*xr = 1.5 * sum_p (0.4att)*xr
    float ciA, ciB;
    {
        u64 cA = 0ull, cB = 0ull;
        #pragma unroll
        for (int k = 0; k < 8; ++k) {
            FMA_F32X2(cA, at2[k], xrA[k], cA);
            FMA_F32X2(cB, at2[k], xrB[k], cB);
        }
        float lo, hi;
        unpack2(cA, lo, hi); ciA = 1.5f * (lo + hi);
        unpack2(cB, lo, hi); ciB = 1.5f * (lo + hi);
    }

    u64 accA[8], accB[8];
    #pragma unroll
    for (int k = 0; k < 8; ++k) { accA[k] = 0ull; accB[k] = 0ull; }
    float sA = 0.f, sB = 0.f;

    __syncthreads();  // scl ready

    unsigned mA[2], mB[2];
    mA[0] = smask[il * 2];        mA[1] = smask[il * 2 + 1];
    mB[0] = smask[(il + 64) * 2]; mB[1] = smask[(il + 64) * 2 + 1];

    const u64 ABSM = 0x7FFFFFFF7FFFFFFFull;

    #pragma unroll 1
    for (int w2 = 0; w2 < CHUNK / 32; ++w2) {
        unsigned maskA = mA[w2], maskB = mB[w2];
        #pragma unroll 4
        for (int jb = 0; jb < 32; ++jb) {
            int jj = w2 * 32 + jb;
            const ulonglong2* xp =
                reinterpret_cast<const ulonglong2*>(&sxl[jj * Dm + h * Pp]);
            u64 xl2[8];
            #pragma unroll
            for (int q = 0; q < 4; ++q) {
                ulonglong2 u = xp[q];
                xl2[2 * q] = u.x; xl2[2 * q + 1] = u.y;
            }
            float cj = scl[jj * Hh + h];

            u64 eA2 = 0ull, eB2 = 0ull;
            #pragma unroll
            for (int k = 0; k < 8; ++k) {
                u64 vA; ADD_F32X2(vA, xrA[k], xl2[k]);
                vA &= ABSM;
                FMA_F32X2(eA2, at2[k], vA, eA2);
                u64 vB; ADD_F32X2(vB, xrB[k], xl2[k]);
                vB &= ABSM;
                FMA_F32X2(eB2, at2[k], vB, eB2);
            }
            float lo, hi;
            unpack2(eA2, lo, hi);
            float eA = (ciA + cj) + (lo + hi);
            unpack2(eB2, lo, hi);
            float eB = (ciB + cj) + (lo + hi);

            float wA = ((maskA >> jb) & 1u) ? __expf(eA) : 0.0f;
            float wB = ((maskB >> jb) & 1u) ? __expf(eB) : 0.0f;
            sA += wA; sB += wB;
            u64 wA2 = pack2(wA, wA);
            u64 wB2 = pack2(wB, wB);
            #pragma unroll
            for (int k = 0; k < 8; ++k) {
                FMA_F32X2(accA[k], wA2, xl2[k], accA[k]);
                FMA_F32X2(accB[k], wB2, xl2[k], accB[k]);
            }
        }
    }

    // store partials
    {
        ulonglong2* pA = reinterpret_cast<ulonglong2*>(
            g_pacc + ((size_t)(split * Bq + b) * Nq + iA) * Dm + h * Pp);
        ulonglong2* pB = reinterpret_cast<ulonglong2*>(
            g_pacc + ((size_t)(split * Bq + b) * Nq + iB) * Dm + h * Pp);
        #pragma unroll
        for (int q = 0; q < 4; ++q) {
            pA[q] = make_ulonglong2(accA[2 * q], accA[2 * q + 1]);
            pB[q] = make_ulonglong2(accB[2 * q], accB[2 * q + 1]);
        }
    }
    g_ps[((split * Bq + b) * Nq + iA) * Hh + h] = sA;
    g_ps[((split * Bq + b) * Nq + iB) * Hh + h] = sB;
}

// ---------------- 5) combine splits, normalize, bias, (relu) ---------------
__global__ void combine_kernel(const float* __restrict__ bias,
                               float* __restrict__ outext, int mode) {
    int id = blockIdx.x * blockDim.x + threadIdx.x;  // Bq*Nq*Dm
    if (id >= Bq * Nq * Dm) return;
    int c = id & (Dm - 1);
    int row = id >> 6;  // b*Nq + i
    int h = c >> 4;
    float s = 0.f, a = 0.f;
    #pragma unroll
    for (int sp = 0; sp < SPLITS; ++sp) {
        s += g_ps[(sp * Bq * Nq + row) * Hh + h];
        a += g_pacc[((size_t)sp * Bq * Nq + row) * Dm + c];
    }
    float o = a / s + bias[c];
    if (mode) {
        g_hbuf[id] = fmaxf(o, 0.0f);
    } else {
        outext[id] = o;
    }
}

// ---------------- driver ----------------------------------------------------
extern "C" void kernel_launch(void* const* d_in, const int* in_sizes, int n_in,
                              void* d_out, int out_size) {
    const float* x    = (const float*)d_in[0];
    const float* emb  = (const float*)d_in[1];
    const float* Wl1  = (const float*)d_in[2];
    const float* Wr1  = (const float*)d_in[3];
    const float* att1 = (const float*)d_in[4];
    const float* b1   = (const float*)d_in[5];
    const float* Wl2  = (const float*)d_in[6];
    const float* Wr2  = (const float*)d_in[7];
    const float* att2 = (const float*)d_in[8];
    const float* b2   = (const float*)d_in[9];
    float* out = (float*)d_out;

    norm_kernel<<<(Nq + 255) / 256, 256>>>(emb);
    mask_kernel<<<Nq / 8, 256>>>();

    dim3 agrid(Nq / TI, Bq, SPLITS);

    // ---- layer 1 ----
    gemm_dual<<<Bq * Nq / 16, 128>>>(x, 0, Wl1, Wr1);
    attn_kernel<<<agrid, 256>>>(att1);
    combine_kernel<<<(Bq * Nq * Dm + 255) / 256, 256>>>(b1, out, 1);

    // ---- layer 2 ----
    gemm_dual<<<Bq * Nq / 16, 128>>>(x, 1, Wl2, Wr2);
    attn_kernel<<<agrid, 256>>>(att2);
    combine_kernel<<<(Bq * Nq * Dm + 255) / 256, 256>>>(b2, out, 0);
}

// round 17
// speedup vs baseline: 1.3168x; 1.3150x over previous
#include <cuda_runtime.h>
#include <math.h>

// Problem constants (fixed shapes from reference)
#define Bq 2
#define Nq 1024
#define DIN 64
#define Hh 4
#define Pp 16
#define Dm 64                // Hh*Pp
#define SPLITS 16
#define CHUNK (Nq / SPLITS)  // 64 j per split
#define TI 128               // i rows per block (2 per thread)
#define NW (Nq / 32)         // mask words per row = 32

typedef unsigned long long u64;

#define ADD_F32X2(d, a, b) \
    asm("add.rn.f32x2 %0, %1, %2;" : "=l"(d) : "l"(a), "l"(b))
#define FMA_F32X2(d, a, b, c) \
    asm("fma.rn.f32x2 %0, %1, %2, %3;" : "=l"(d) : "l"(a), "l"(b), "l"(c))

__device__ __forceinline__ u64 pack2(float lo, float hi) {
    u64 d;
    asm("mov.b64 %0, {%1, %2};" : "=l"(d) : "r"(__float_as_uint(lo)), "r"(__float_as_uint(hi)));
    return d;
}
__device__ __forceinline__ void unpack2(u64 v, float& lo, float& hi) {
    unsigned a, b;
    asm("mov.b64 {%0, %1}, %2;" : "=r"(a), "=r"(b) : "l"(v));
    lo = __uint_as_float(a);
    hi = __uint_as_float(b);
}

// ---------------- scratch (device globals; no allocation allowed) ----------
__device__ float               g_ne[Nq * DIN];
__device__ unsigned            g_mask[Nq * NW];
__device__ __align__(16) float g_xl[Bq * Nq * Dm];
__device__ __align__(16) float g_xr[Bq * Nq * Dm];
__device__ __align__(16) float g_pacc[(size_t)SPLITS * Bq * Nq * Dm];  // 8 MB
__device__ float               g_ps[SPLITS * Bq * Nq * Hh];

// ---------------- 1) normalize embedding rows ------------------------------
__global__ void norm_kernel(const float* __restrict__ emb) {
    int r = blockIdx.x * blockDim.x + threadIdx.x;
    if (r >= Nq) return;
    float s = 0.f;
    #pragma unroll 8
    for (int k = 0; k < DIN; ++k) {
        float v = emb[r * DIN + k];
        s = fmaf(v, v, s);
    }
    float n = fmaxf(sqrtf(s), 1e-12f);
    float inv = 1.0f / n;
    #pragma unroll 8
    for (int k = 0; k < DIN; ++k)
        g_ne[r * DIN + k] = emb[r * DIN + k] * inv;
}

// ---------------- 2) mask: (ne_i . ne_j != 0) || (i==j) --------------------
// Register-tiled: block = 256 threads = 8 warps; warp handles 4 i-rows x 32 j.
// Block covers 32 i-rows x 256 j-cols. grid (32, 4).
__global__ void __launch_bounds__(256) mask_kernel() {
    __shared__ float shi[32][68];   // padded rows (68*4 = 272 = 17*16 B, f4-ok)
    __shared__ float shj[32][68];
    int t = threadIdx.x;
    int i0 = blockIdx.x * 32;
    int jt0 = blockIdx.y * 8;       // 8 j-tiles of 32

    for (int k = t; k < 32 * DIN; k += 256)
        shi[k >> 6][k & 63] = g_ne[i0 * DIN + k];

    int w = t >> 5, lane = t & 31;

    for (int jt = jt0; jt < jt0 + 8; ++jt) {
        __syncthreads();
        for (int k = t; k < 32 * DIN; k += 256)
            shj[k >> 6][k & 63] = g_ne[(jt * 32) * DIN + k];
        __syncthreads();

        float acc0 = 0.f, acc1 = 0.f, acc2 = 0.f, acc3 = 0.f;
        #pragma unroll
        for (int kq = 0; kq < DIN; kq += 4) {
            float4 bj = *reinterpret_cast<const float4*>(&shj[lane][kq]);
            float4 a0 = *reinterpret_cast<const float4*>(&shi[w * 4 + 0][kq]);
            float4 a1 = *reinterpret_cast<const float4*>(&shi[w * 4 + 1][kq]);
            float4 a2 = *reinterpret_cast<const float4*>(&shi[w * 4 + 2][kq]);
            float4 a3 = *reinterpret_cast<const float4*>(&shi[w * 4 + 3][kq]);
            acc0 = fmaf(a0.x, bj.x, fmaf(a0.y, bj.y, fmaf(a0.z, bj.z, fmaf(a0.w, bj.w, acc0))));
            acc1 = fmaf(a1.x, bj.x, fmaf(a1.y, bj.y, fmaf(a1.z, bj.z, fmaf(a1.w, bj.w, acc1))));
            acc2 = fmaf(a2.x, bj.x, fmaf(a2.y, bj.y, fmaf(a2.z, bj.z, fmaf(a2.w, bj.w, acc2))));
            acc3 = fmaf(a3.x, bj.x, fmaf(a3.y, bj.y, fmaf(a3.z, bj.z, fmaf(a3.w, bj.w, acc3))));
        }
        int j = jt * 32 + lane;
        float accs[4] = {acc0, acc1, acc2, acc3};
        #pragma unroll
        for (int ii = 0; ii < 4; ++ii) {
            int i = i0 + w * 4 + ii;
            bool bit = (accs[ii] != 0.0f) || (i == j);
            unsigned word = __ballot_sync(0xffffffffu, bit);
            if (lane == 0) g_mask[i * NW + jt] = word;
        }
    }
}

// ---------------- 3) dual GEMM (layer 1): xl = X@Wl, xr = X@Wr -------------
__global__ void gemm_dual(const float* __restrict__ X,
                          const float* __restrict__ Wl,
                          const float* __restrict__ Wr) {
    __shared__ float xs[16][DIN];
    int t = threadIdx.x;  // 128
    int row0 = blockIdx.x * 16;
    for (int k = t; k < 16 * DIN; k += 128)
        xs[k / DIN][k % DIN] = X[row0 * DIN + k];
    __syncthreads();
    const float* W = (t < 64) ? Wl : Wr;
    int col = t & 63;
    float wreg[DIN];
    #pragma unroll
    for (int k = 0; k < DIN; ++k) wreg[k] = W[k * Dm + col];
    float* out = (t < 64) ? g_xl : g_xr;
    for (int r = 0; r < 16; ++r) {
        float a = 0.f;
        #pragma unroll
        for (int k = 0; k < DIN; ++k) a = fmaf(xs[r][k], wreg[k], a);
        out[(row0 + r) * Dm + col] = a;
    }
}

// ---------------- 4) fused attention (per j-split partials) ----------------
// block: 256 threads = 64 i-slots x 4 h; each thread handles 2 i rows.
// grid (Nq/TI, Bq, SPLITS)
__global__ void __launch_bounds__(256, 2) attn_kernel(const float* __restrict__ att) {
    __shared__ __align__(16) float sxl[CHUNK * Dm];   // 16 KB
    __shared__ float scl[CHUNK * Hh];                 // 1 KB
    __shared__ unsigned smask[TI * (CHUNK / 32)];     // 128*2

    int t = threadIdx.x;
    int b = blockIdx.y, split = blockIdx.z;
    int i0 = blockIdx.x * TI;
    int j0 = split * CHUNK;

    // stage xl j-chunk into shared
    {
        const float4* src = reinterpret_cast<const float4*>(g_xl + (size_t)(b * Nq + j0) * Dm);
        float4* dst = reinterpret_cast<float4*>(sxl);
        for (int k = t; k < CHUNK * Dm / 4; k += 256) dst[k] = src[k];
    }
    // stage mask words (TI rows x 2 words = 256)
    {
        int il = t >> 1, ww = t & 1;
        smask[t] = g_mask[(i0 + il) * NW + (j0 >> 5) + ww];
    }
    __syncthreads();
    // scl[jj,h] = 0.6 * sum_p att[h,p] * xl[j0+jj, h, p]   (one thread each)
    {
        int jj = t >> 2, hh = t & 3;
        float c = 0.f;
        #pragma unroll
        for (int p = 0; p < Pp; ++p)
            c = fmaf(att[hh * Pp + p], sxl[jj * Dm + hh * Pp + p], c);
        scl[jj * Hh + hh] = 0.6f * c;
    }

    int il = t >> 2, h = t & 3;
    int iA = i0 + il;
    int iB = i0 + il + 64;

    // packed 0.4*att for this head
    u64 at2[8];
    #pragma unroll
    for (int k = 0; k < 8; ++k)
        at2[k] = pack2(0.4f * att[h * Pp + 2 * k], 0.4f * att[h * Pp + 2 * k + 1]);

    // packed xr rows for both i
    u64 xrA[8], xrB[8];
    {
        const ulonglong2* pA =
            reinterpret_cast<const ulonglong2*>(g_xr + ((size_t)(b * Nq + iA)) * Dm + h * Pp);
        const ulonglong2* pB =
            reinterpret_cast<const ulonglong2*>(g_xr + ((size_t)(b * Nq + iB)) * Dm + h * Pp);
        #pragma unroll
        for (int q = 0; q < 4; ++q) {
            ulonglong2 ua = pA[q];
            xrA[2 * q] = ua.x; xrA[2 * q + 1] = ua.y;
            ulonglong2 ub = pB[q];
            xrB[2 * q] = ub.x; xrB[2 * q + 1] = ub.y;
        }
    }

    // ci = 0.6 * sum_p att*xr = 1.5 * sum_p (0.4att)*xr
    float ciA, ciB;
    {
        u64 cA = 0ull, cB = 0ull;
        #pragma unroll
        for (int k = 0; k < 8; ++k) {
            FMA_F32X2(cA, at2[k], xrA[k], cA);
            FMA_F32X2(cB, at2[k], xrB[k], cB);
        }
        float lo, hi;
        unpack2(cA, lo, hi); ciA = 1.5f * (lo + hi);
        unpack2(cB, lo, hi); ciB = 1.5f * (lo + hi);
    }

    u64 accA[8], accB[8];
    #pragma unroll
    for (int k = 0; k < 8; ++k) { accA[k] = 0ull; accB[k] = 0ull; }
    float sA = 0.f, sB = 0.f;

    __syncthreads();  // scl ready

    unsigned mA[2], mB[2];
    mA[0] = smask[il * 2];        mA[1] = smask[il * 2 + 1];
    mB[0] = smask[(il + 64) * 2]; mB[1] = smask[(il + 64) * 2 + 1];

    const u64 ABSM = 0x7FFFFFFF7FFFFFFFull;

    #pragma unroll 1
    for (int w2 = 0; w2 < CHUNK / 32; ++w2) {
        unsigned maskA = mA[w2], maskB = mB[w2];
        #pragma unroll 4
        for (int jb = 0; jb < 32; ++jb) {
            int jj = w2 * 32 + jb;
            const ulonglong2* xp =
                reinterpret_cast<const ulonglong2*>(&sxl[jj * Dm + h * Pp]);
            u64 xl2[8];
            #pragma unroll
            for (int q = 0; q < 4; ++q) {
                ulonglong2 u = xp[q];
                xl2[2 * q] = u.x; xl2[2 * q + 1] = u.y;
            }
            float cj = scl[jj * Hh + h];

            // score: two independent accumulation chains per row
            u64 eA0 = 0ull, eA1 = 0ull, eB0 = 0ull, eB1 = 0ull;
            #pragma unroll
            for (int k = 0; k < 4; ++k) {
                u64 v0; ADD_F32X2(v0, xrA[k], xl2[k]);
                v0 &= ABSM;
                FMA_F32X2(eA0, at2[k], v0, eA0);
                u64 v1; ADD_F32X2(v1, xrA[k + 4], xl2[k + 4]);
                v1 &= ABSM;
                FMA_F32X2(eA1, at2[k + 4], v1, eA1);
                u64 v2; ADD_F32X2(v2, xrB[k], xl2[k]);
                v2 &= ABSM;
                FMA_F32X2(eB0, at2[k], v2, eB0);
                u64 v3; ADD_F32X2(v3, xrB[k + 4], xl2[k + 4]);
                v3 &= ABSM;
                FMA_F32X2(eB1, at2[k + 4], v3, eB1);
            }
            u64 eA2; ADD_F32X2(eA2, eA0, eA1);
            u64 eB2; ADD_F32X2(eB2, eB0, eB1);
            float lo, hi;
            unpack2(eA2, lo, hi);
            float eA = (ciA + cj) + (lo + hi);
            unpack2(eB2, lo, hi);
            float eB = (ciB + cj) + (lo + hi);

            float wA = ((maskA >> jb) & 1u) ? __expf(eA) : 0.0f;
            float wB = ((maskB >> jb) & 1u) ? __expf(eB) : 0.0f;
            sA += wA; sB += wB;
            u64 wA2 = pack2(wA, wA);
            u64 wB2 = pack2(wB, wB);
            #pragma unroll
            for (int k = 0; k < 8; ++k) {
                FMA_F32X2(accA[k], wA2, xl2[k], accA[k]);
                FMA_F32X2(accB[k], wB2, xl2[k], accB[k]);
            }
        }
    }

    // store partials
    {
        ulonglong2* pA = reinterpret_cast<ulonglong2*>(
            g_pacc + ((size_t)(split * Bq + b) * Nq + iA) * Dm + h * Pp);
        ulonglong2* pB = reinterpret_cast<ulonglong2*>(
            g_pacc + ((size_t)(split * Bq + b) * Nq + iB) * Dm + h * Pp);
        #pragma unroll
        for (int q = 0; q < 4; ++q) {
            pA[q] = make_ulonglong2(accA[2 * q], accA[2 * q + 1]);
            pB[q] = make_ulonglong2(accB[2 * q], accB[2 * q + 1]);
        }
    }
    g_ps[((split * Bq + b) * Nq + iA) * Hh + h] = sA;
    g_ps[((split * Bq + b) * Nq + iB) * Hh + h] = sB;
}

// ---------------- 5) fused: combine layer-1 (+relu) then layer-2 dual GEMM -
// block = 128 threads, 16 rows. h tile never touches global memory.
__global__ void __launch_bounds__(128) combine_gemm_kernel(
        const float* __restrict__ bias,
        const float* __restrict__ Wl, const float* __restrict__ Wr) {
    __shared__ float xs[16][DIN];
    __shared__ float sinv[16 * Hh];
    int t = threadIdx.x;  // 128
    int row0 = blockIdx.x * 16;

    if (t < 64) {
        int r = t >> 2, h = t & 3;
        int row = row0 + r;
        float s = 0.f;
        #pragma unroll
        for (int sp = 0; sp < SPLITS; ++sp)
            s += g_ps[(sp * Bq * Nq + row) * Hh + h];
        sinv[t] = 1.0f / s;
    }
    __syncthreads();

    for (int e = t; e < 16 * Dm; e += 128) {
        int r = e >> 6, c = e & 63;
        int row = row0 + r;
        float a = 0.f;
        #pragma unroll
        for (int sp = 0; sp < SPLITS; ++sp)
            a += g_pacc[((size_t)sp * Bq * Nq + row) * Dm + c];
        float o = a * sinv[r * Hh + (c >> 4)] + bias[c];
        xs[r][c] = fmaxf(o, 0.0f);
    }
    __syncthreads();

    const float* W = (t < 64) ? Wl : Wr;
    int col = t & 63;
    float wreg[DIN];
    #pragma unroll
    for (int k = 0; k < DIN; ++k) wreg[k] = W[k * Dm + col];
    float* out = (t < 64) ? g_xl : g_xr;
    for (int r = 0; r < 16; ++r) {
        float a = 0.f;
        #pragma unroll
        for (int k = 0; k < DIN; ++k) a = fmaf(xs[r][k], wreg[k], a);
        out[(row0 + r) * Dm + col] = a;
    }
}

// ---------------- 6) final combine: normalize + bias -> output -------------
__global__ void combine_kernel(const float* __restrict__ bias,
                               float* __restrict__ outext) {
    int id = blockIdx.x * blockDim.x + threadIdx.x;  // Bq*Nq*Dm
    if (id >= Bq * Nq * Dm) return;
    int c = id & (Dm - 1);
    int row = id >> 6;  // b*Nq + i
    int h = c >> 4;
    float s = 0.f, a = 0.f;
    #pragma unroll
    for (int sp = 0; sp < SPLITS; ++sp) {
        s += g_ps[(sp * Bq * Nq + row) * Hh + h];
        a += g_pacc[((size_t)sp * Bq * Nq + row) * Dm + c];
    }
    outext[id] = a / s + bias[c];
}

// ---------------- driver ----------------------------------------------------
extern "C" void kernel_launch(void* const* d_in, const int* in_sizes, int n_in,
                              void* d_out, int out_size) {
    const float* x    = (const float*)d_in[0];
    const float* emb  = (const float*)d_in[1];
    const float* Wl1  = (const float*)d_in[2];
    const float* Wr1  = (const float*)d_in[3];
    const float* att1 = (const float*)d_in[4];
    const float* b1   = (const float*)d_in[5];
    const float* Wl2  = (const float*)d_in[6];
    const float* Wr2  = (const float*)d_in[7];
    const float* att2 = (const float*)d_in[8];
    const float* b2   = (const float*)d_in[9];
    float* out = (float*)d_out;

    norm_kernel<<<(Nq + 255) / 256, 256>>>(emb);
    mask_kernel<<<dim3(Nq / 32, 4), 256>>>();

    dim3 agrid(Nq / TI, Bq, SPLITS);

    // ---- layer 1 ----
    gemm_dual<<<Bq * Nq / 16, 128>>>(x, Wl1, Wr1);
    attn_kernel<<<agrid, 256>>>(att1);

    // ---- combine layer 1 + gemm layer 2 (fused) ----
    combine_gemm_kernel<<<Bq * Nq / 16, 128>>>(b1, Wl2, Wr2);

    // ---- layer 2 ----
    attn_kernel<<<agrid, 256>>>(att2);
    combine_kernel<<<(Bq * Nq * Dm + 255) / 256, 256>>>(b2, out);
}